// round 7
// baseline (speedup 1.0000x reference)
#include <cuda_runtime.h>

// ---------------- problem constants ----------------
#define UN   100000
#define INUM 50000
#define NNZE 1000000
#define NROWS_TOT (UN + INUM + UN)     // 250000

// ---------------- routed sparse pointers ----------------
__device__ const int*   g_rows[3];
__device__ const int*   g_cols[3];
__device__ const float* g_vals[3];

// ---------------- scratch ----------------
__device__ unsigned g_cnt[NROWS_TOT];          // zeroed each replay (memset)
__device__ float    g_scr[3 * 4096];           // zeroed inside route kernel
__device__ unsigned g_slot[3 * NNZE];          // per-edge slot within row
__device__ unsigned g_rowstart[NROWS_TOT + 3];
__device__ unsigned long long g_csr[3 * NNZE]; // packed (val<<32 | col)
__device__ float    g_spbuf[32000000];
__device__ float    g_t2[3 * 8192];

#define Z_TU1 0
#define Z_TU2 6400000
#define Z_UU1 12800000
#define Z_UU2 19200000
#define Z_TI1 25600000
#define Z_TI2 28800000

// ---------------- router + scr zero (blocks 0..47 zero g_scr; block 48 routes) ----------------
__global__ void route_kernel(const void* a8, const void* a9, const void* a10,
                             const void* a11, const void* a12, const void* a13,
                             const void* a14, const void* a15, const void* a16)
{
    if (blockIdx.x < 48) {
        int i = blockIdx.x * 256 + threadIdx.x;
        if (i < 3 * 4096) g_scr[i] = 0.f;
        return;
    }
    if (threadIdx.x != 0) return;
    const unsigned* p = (const unsigned*)a8;
    unsigned m = 0;
    for (int i = 0; i < 32; ++i) { unsigned v = p[i]; m = (v > m) ? v : m; }
    if (m > 0x01000000u) {
        g_vals[0] = (const float*)a8;  g_vals[1] = (const float*)a9;  g_vals[2] = (const float*)a10;
        g_rows[0] = (const int*)a11;   g_cols[0] = (const int*)a12;
        g_rows[1] = (const int*)a13;   g_cols[1] = (const int*)a14;
        g_rows[2] = (const int*)a15;   g_cols[2] = (const int*)a16;
    } else {
        g_rows[0] = (const int*)a8;   g_cols[0] = (const int*)a9;   g_vals[0] = (const float*)a10;
        g_rows[1] = (const int*)a11;  g_cols[1] = (const int*)a12;  g_vals[1] = (const float*)a13;
        g_rows[2] = (const int*)a14;  g_cols[2] = (const int*)a15;  g_vals[2] = (const float*)a16;
    }
}

// ---------------- CSR build: histogram + record slot ----------------
__global__ void hist3_kernel()
{
    int e = blockIdx.x * 256 + threadIdx.x;
    if (e >= 3 * NNZE) return;
    int m = (e >= 2 * NNZE) ? 2 : ((e >= NNZE) ? 1 : 0);
    int i = e - m * NNZE;
    int cb = (m == 0) ? 0 : ((m == 1) ? UN : UN + INUM);
    int r = __ldg(&g_rows[m][i]);
    g_slot[e] = atomicAdd(&g_cnt[cb + r], 1u);
}

// ---------------- CSR build: 3 exclusive scans (one block each) ----------------
__global__ void scan3_kernel()
{
    __shared__ unsigned sPart[1024];
    int m = blockIdx.x;
    int Nm  = (m == 1) ? INUM : UN;
    int cb  = (m == 0) ? 0 : ((m == 1) ? UN : UN + INUM);
    int rb  = (m == 0) ? 0 : ((m == 1) ? UN + 1 : UN + INUM + 2);
    int t = threadIdx.x;
    int chunk = (Nm + 1023) >> 10;
    int lo = t * chunk; if (lo > Nm) lo = Nm;
    int hi = lo + chunk; if (hi > Nm) hi = Nm;
    unsigned s = 0;
    for (int i = lo; i < hi; ++i) s += g_cnt[cb + i];
    sPart[t] = s;
    __syncthreads();
    for (int d = 1; d < 1024; d <<= 1) {
        unsigned v = (t >= d) ? sPart[t - d] : 0u;
        __syncthreads();
        sPart[t] += v;
        __syncthreads();
    }
    unsigned run = (t == 0) ? 0u : sPart[t - 1];
    for (int i = lo; i < hi; ++i) {
        unsigned c = g_cnt[cb + i];
        g_rowstart[rb + i] = run;
        run += c;
    }
    if (t == 1023) g_rowstart[rb + Nm] = run;
}

// ---------------- CSR build: scatter (no atomics) ----------------
__global__ void scatter3_kernel()
{
    int e = blockIdx.x * 256 + threadIdx.x;
    if (e >= 3 * NNZE) return;
    int m = (e >= 2 * NNZE) ? 2 : ((e >= NNZE) ? 1 : 0);
    int i = e - m * NNZE;
    int rb = (m == 0) ? 0 : ((m == 1) ? UN + 1 : UN + INUM + 2);
    int   r = __ldg(&g_rows[m][i]);
    int   c = __ldg(&g_cols[m][i]);
    float v = __ldg(&g_vals[m][i]);
    unsigned idx = __ldg(&g_rowstart[rb + r]) + g_slot[e];
    g_csr[(size_t)m * NNZE + idx] =
        ((unsigned long long)__float_as_uint(v) << 32) | (unsigned)c;
}

// ---------------- gather SpMM: 3 matrices, 16 lanes per row, no atomics, 4-wide ILP ----------------
__global__ void __launch_bounds__(256) gather3_kernel(
    const float* __restrict__ X0, const float* __restrict__ X1, const float* __restrict__ X2,
    float* __restrict__ O0, float* __restrict__ O1, float* __restrict__ O2)
{
    int gr = blockIdx.x * 16 + (threadIdx.x >> 4);
    int lane = threadIdx.x & 15;
    int m, r, rb;
    const float* X; float* O;
    if (gr < UN)              { m = 0; r = gr;             rb = 0;              X = X0; O = O0; }
    else if (gr < UN + INUM)  { m = 1; r = gr - UN;        rb = UN + 1;         X = X1; O = O1; }
    else                      { m = 2; r = gr - UN - INUM; rb = UN + INUM + 2;  X = X2; O = O2; }
    unsigned s = __ldg(&g_rowstart[rb + r]);
    unsigned e = __ldg(&g_rowstart[rb + r + 1]);
    const unsigned long long* csr = g_csr + (size_t)m * NNZE;
    float4 accA = make_float4(0.f, 0.f, 0.f, 0.f);
    float4 accB = make_float4(0.f, 0.f, 0.f, 0.f);
    unsigned i = s;
    for (; i + 4 <= e; i += 4) {
        unsigned long long u0 = __ldg(&csr[i]);
        unsigned long long u1 = __ldg(&csr[i + 1]);
        unsigned long long u2 = __ldg(&csr[i + 2]);
        unsigned long long u3 = __ldg(&csr[i + 3]);
        float4 x0 = __ldg((const float4*)X + (size_t)(unsigned)(u0 & 0xffffffffu) * 16 + lane);
        float4 x1 = __ldg((const float4*)X + (size_t)(unsigned)(u1 & 0xffffffffu) * 16 + lane);
        float4 x2 = __ldg((const float4*)X + (size_t)(unsigned)(u2 & 0xffffffffu) * 16 + lane);
        float4 x3 = __ldg((const float4*)X + (size_t)(unsigned)(u3 & 0xffffffffu) * 16 + lane);
        float v0 = __uint_as_float((unsigned)(u0 >> 32));
        float v1 = __uint_as_float((unsigned)(u1 >> 32));
        float v2 = __uint_as_float((unsigned)(u2 >> 32));
        float v3 = __uint_as_float((unsigned)(u3 >> 32));
        accA.x += v0 * x0.x; accA.y += v0 * x0.y; accA.z += v0 * x0.z; accA.w += v0 * x0.w;
        accB.x += v1 * x1.x; accB.y += v1 * x1.y; accB.z += v1 * x1.z; accB.w += v1 * x1.w;
        accA.x += v2 * x2.x; accA.y += v2 * x2.y; accA.z += v2 * x2.z; accA.w += v2 * x2.w;
        accB.x += v3 * x3.x; accB.y += v3 * x3.y; accB.z += v3 * x3.z; accB.w += v3 * x3.w;
    }
    for (; i < e; ++i) {
        unsigned long long u0 = __ldg(&csr[i]);
        float v0 = __uint_as_float((unsigned)(u0 >> 32));
        float4 x0 = __ldg((const float4*)X + (size_t)(unsigned)(u0 & 0xffffffffu) * 16 + lane);
        accA.x += v0 * x0.x; accA.y += v0 * x0.y; accA.z += v0 * x0.z; accA.w += v0 * x0.w;
    }
    ((float4*)O)[(size_t)r * 16 + lane] =
        make_float4(accA.x + accB.x, accA.y + accB.y, accA.z + accB.z, accA.w + accB.w);
}

// ---------------- copy the 3 Hyper outputs ----------------
__global__ void copy_hyper_kernel(const float* __restrict__ Hyp,
                                  float* o0, float* o1, float* o2)
{
    int i = blockIdx.x * 256 + threadIdx.x;
    if (i < 8192) { o0[i] = Hyp[i]; o1[i] = Hyp[8192 + i]; o2[i] = Hyp[16384 + i]; }
}

// ---------------- fused embed+key+vp+Gram (64-row chunks, 8x(2+2) tiles) ----------------
// smem floats: sK[4096] | sPV[4096] | sE[64*65] | sKy[64*65] | sVP[64*65]
__global__ void __launch_bounds__(256) embed_key_vk_kernel(
    const float* __restrict__ A, const float* __restrict__ B1, const float* __restrict__ B2,
    const float* __restrict__ Kmat, const float* __restrict__ pV,
    float* __restrict__ E0, float* __restrict__ Key, float* __restrict__ VK, int N)
{
    extern __shared__ float sm[];
    float* sK  = sm;
    float* sPV = sm + 4096;
    float* sE  = sm + 8192;          // [64][65]
    float* sKy = sE + 64 * 65;
    float* sVP = sKy + 64 * 65;
    int tid = threadIdx.x;
    for (int i = tid; i < 4096; i += 256) { sK[i] = Kmat[i]; sPV[i] = pV[i]; }
    int rg = tid >> 5;               // 0..7 -> rows rg*8..+7
    int tx = tid & 31;
    int c0 = tx, c1 = tx + 32;
    int hg = tid >> 6, pi = (tid >> 3) & 7, pj = tid & 7;
    float g00 = 0.f, g01 = 0.f, g10 = 0.f, g11 = 0.f;
    __syncthreads();
    int nChunks = (N + 63) >> 6;
    for (int chunk = blockIdx.x; chunk < nChunks; chunk += gridDim.x) {
        int n0 = chunk << 6;
        #pragma unroll
        for (int q = 0; q < 4; ++q) {
            int idx = tid + q * 256;        // float4 index 0..1023
            int r = idx >> 4, cc = idx & 15;
            int n = n0 + r;
            float4 v = make_float4(0.f, 0.f, 0.f, 0.f);
            if (n < N) {
                float4 a = __ldg((const float4*)A  + (size_t)n * 16 + cc);
                float4 b = __ldg((const float4*)B1 + (size_t)n * 16 + cc);
                float4 d = __ldg((const float4*)B2 + (size_t)n * 16 + cc);
                v = make_float4(a.x + b.x + d.x, a.y + b.y + d.y,
                                a.z + b.z + d.z, a.w + b.w + d.w);
                ((float4*)E0)[(size_t)n * 16 + cc] = v;
            }
            sE[r * 65 + cc * 4 + 0] = v.x; sE[r * 65 + cc * 4 + 1] = v.y;
            sE[r * 65 + cc * 4 + 2] = v.z; sE[r * 65 + cc * 4 + 3] = v.w;
        }
        __syncthreads();
        float ka[8][2], pa[8][2];
        #pragma unroll
        for (int rr = 0; rr < 8; ++rr) { ka[rr][0]=ka[rr][1]=pa[rr][0]=pa[rr][1]=0.f; }
        #pragma unroll 8
        for (int k = 0; k < 64; ++k) {
            float w0 = sK[k * 64 + c0],  w1 = sK[k * 64 + c1];
            float p0 = sPV[k * 64 + c0], p1 = sPV[k * 64 + c1];
            #pragma unroll
            for (int rr = 0; rr < 8; ++rr) {
                float ev = sE[(rg * 8 + rr) * 65 + k];
                ka[rr][0] += ev * w0; ka[rr][1] += ev * w1;
                pa[rr][0] += ev * p0; pa[rr][1] += ev * p1;
            }
        }
        int h0 = c0 >> 4, j0 = c0 & 15, h1 = c1 >> 4, j1 = c1 & 15;
        size_t kb0 = (size_t)h0 * N * 16, kb1 = (size_t)h1 * N * 16;
        #pragma unroll
        for (int rr = 0; rr < 8; ++rr) {
            int rrow = rg * 8 + rr;
            sKy[rrow * 65 + c0] = ka[rr][0]; sKy[rrow * 65 + c1] = ka[rr][1];
            sVP[rrow * 65 + c0] = pa[rr][0]; sVP[rrow * 65 + c1] = pa[rr][1];
            int n = n0 + rrow;
            if (n < N) {
                Key[kb0 + (size_t)n * 16 + j0] = ka[rr][0];
                Key[kb1 + (size_t)n * 16 + j1] = ka[rr][1];
            }
        }
        __syncthreads();
        int ca0 = hg * 16 + 2 * pi, cb0 = hg * 16 + 2 * pj;
        #pragma unroll 8
        for (int r = 0; r < 64; ++r) {
            float va0 = sVP[r * 65 + ca0], va1 = sVP[r * 65 + ca0 + 1];
            float vb0 = sKy[r * 65 + cb0], vb1 = sKy[r * 65 + cb0 + 1];
            g00 += va0 * vb0; g01 += va0 * vb1;
            g10 += va1 * vb0; g11 += va1 * vb1;
        }
        __syncthreads();
    }
    atomicAdd(&VK[hg * 256 + (2 * pi    ) * 16 + 2 * pj    ], g00);
    atomicAdd(&VK[hg * 256 + (2 * pi    ) * 16 + 2 * pj + 1], g01);
    atomicAdd(&VK[hg * 256 + (2 * pi + 1) * 16 + 2 * pj    ], g10);
    atomicAdd(&VK[hg * 256 + (2 * pi + 1) * 16 + 2 * pj + 1], g11);
}

__device__ __forceinline__ float leaky_f(float x) { return (x >= 0.f) ? x : 0.5f * x; }

// ---------------- batched t1t2 ----------------
__global__ void t1t2_all_kernel(const float* __restrict__ Hyp, const float* __restrict__ W1base,
                                int layer)
{
    __shared__ float sVK[1024];
    __shared__ float sT1[8192];
    int t = blockIdx.y;
    const float* VK    = g_scr + t * 4096 + layer * 1024;
    const float* Hyper = Hyp + t * 8192;
    const float* W1    = W1base + (size_t)(t * 2 + layer) * 16384;
    float* T2out       = g_t2 + t * 8192;
    int tid = threadIdx.x;
    for (int i = tid; i < 1024; i += 256) sVK[i] = VK[i];
    __syncthreads();
    for (int o = tid; o < 8192; o += 256) {
        int d = o >> 7, k = o & 127;
        int h = d >> 4, i = d & 15;
        float s = 0.f;
        #pragma unroll
        for (int j = 0; j < 16; ++j)
            s += sVK[h * 256 + i * 16 + j] * __ldg(&Hyper[k * 64 + h * 16 + j]);
        sT1[d * 128 + k] = s;
    }
    __syncthreads();
    int kb = blockIdx.x * 8;
    for (int o = tid; o < 512; o += 256) {
        int d = o >> 3, k = kb + (o & 7);
        float s = 0.f;
        #pragma unroll 8
        for (int m = 0; m < 128; ++m) s += sT1[d * 128 + m] * __ldg(&W1[k * 128 + m]);
        T2out[d * 128 + k] = leaky_f(s) + sT1[d * 128 + k];
    }
}

// ---------------- batched t3+pre ----------------
__global__ void t3pre_all_kernel(const float* __restrict__ W2base, const float* __restrict__ Vbase,
                                 const float* __restrict__ Hyp, int layer)
{
    __shared__ float sT2[8192];
    __shared__ float sT3[8][64];
    __shared__ float sP0[8][64];
    int t = blockIdx.y;
    const float* T2    = g_t2 + t * 8192;
    const float* W2    = W2base + (size_t)(t * 2 + layer) * 16384;
    const float* V     = Vbase + t * 4096;
    const float* Hyper = Hyp + t * 8192;
    float* PRE         = g_scr + t * 4096 + 2048 + layer * 1024;
    int tid = threadIdx.x;
    for (int i = tid; i < 8192; i += 256) sT2[i] = T2[i];
    __syncthreads();
    int kb = blockIdx.x * 8;
    for (int o = tid; o < 512; o += 256) {
        int d = o >> 3, kk = o & 7, k = kb + kk;
        float s = 0.f;
        #pragma unroll 8
        for (int m = 0; m < 128; ++m) s += sT2[d * 128 + m] * __ldg(&W2[k * 128 + m]);
        sT3[kk][d] = leaky_f(s) + sT2[d * 128 + k];
    }
    __syncthreads();
    for (int o = tid; o < 512; o += 256) {
        int kk = o >> 6, d2 = o & 63;
        float s = 0.f;
        #pragma unroll 8
        for (int d = 0; d < 64; ++d) s += sT3[kk][d] * __ldg(&V[d * 64 + d2]);
        sP0[kk][d2] = s;
    }
    __syncthreads();
    for (int o = tid; o < 1024; o += 256) {
        int h = o >> 8, i = (o >> 4) & 15, j = o & 15;
        float s = 0.f;
        #pragma unroll
        for (int kk = 0; kk < 8; ++kk)
            s += __ldg(&Hyper[(size_t)(kb + kk) * 64 + h * 16 + i]) * sP0[kk][h * 16 + j];
        atomicAdd(&PRE[o], s);
    }
}

// ---------------- batched layer-0 epilogue + layer-1 prologue (128 rows/block) ----------------
// smem floats: sPre[1024] | sPV[4096] | sNew[128*65] | sKy[128*65] | sVP[128*65]
__global__ void __launch_bounds__(256) newtotal_vk_all_kernel(
    const float* K0, const float* K1, const float* K2,
    const float* E0a, const float* E0b, const float* E0c,
    float* La, float* Lb, float* Lc,
    const float* __restrict__ pVbase)
{
    int t = blockIdx.y;
    int N = (t == 1) ? INUM : UN;
    if (blockIdx.x * 128 >= N) return;
    const float* Key = (t == 0) ? K0 : ((t == 1) ? K1 : K2);
    const float* E0  = (t == 0) ? E0a : ((t == 1) ? E0b : E0c);
    float* lat       = (t == 0) ? La : ((t == 1) ? Lb : Lc);
    const float* PRE = g_scr + t * 4096 + 2048;
    const float* pV  = pVbase + t * 4096;
    float* VK        = g_scr + t * 4096 + 1024;

    extern __shared__ float sm[];
    float* sPre = sm;
    float* sPV  = sm + 1024;
    float* sNew = sm + 5120;             // [128][65]
    float* sKy  = sNew + 128 * 65;
    float* sVP  = sKy + 128 * 65;
    int tid = threadIdx.x;
    for (int i = tid; i < 1024; i += 256) sPre[i] = PRE[i];
    for (int i = tid; i < 4096; i += 256) sPV[i] = pV[i];
    __syncthreads();
    // phase 1: 512 (row,head) pairs, 2 per thread
    #pragma unroll
    for (int q = 0; q < 2; ++q) {
        int p = tid + q * 256;
        int nl = p & 127, h = p >> 7;
        int n = blockIdx.x * 128 + nl;
        bool valid = (n < N);
        float kv[16];
        #pragma unroll
        for (int i = 0; i < 16; ++i) kv[i] = 0.f;
        if (valid) {
            const float4* kp = (const float4*)Key + ((size_t)h * N + n) * 4;
            float4 k0 = __ldg(kp), k1 = __ldg(kp + 1), k2 = __ldg(kp + 2), k3 = __ldg(kp + 3);
            kv[0]=k0.x; kv[1]=k0.y; kv[2]=k0.z; kv[3]=k0.w;
            kv[4]=k1.x; kv[5]=k1.y; kv[6]=k1.z; kv[7]=k1.w;
            kv[8]=k2.x; kv[9]=k2.y; kv[10]=k2.z; kv[11]=k2.w;
            kv[12]=k3.x; kv[13]=k3.y; kv[14]=k3.z; kv[15]=k3.w;
        }
        const float* pb = &sPre[h * 256];
        float o[16];
        #pragma unroll
        for (int j = 0; j < 16; ++j) {
            float s = 0.f;
            #pragma unroll
            for (int i = 0; i < 16; ++i) s += kv[i] * pb[i * 16 + j];
            o[j] = s;
        }
        if (valid) {
            size_t base = (size_t)n * 64 + h * 16;
            const float4* ep = (const float4*)(E0 + base);
            float4* lp = (float4*)(lat + base);
            #pragma unroll
            for (int w = 0; w < 4; ++w) {
                float4 e = __ldg(ep + w);
                lp[w] = make_float4(e.x + o[w*4+0], e.y + o[w*4+1], e.z + o[w*4+2], e.w + o[w*4+3]);
            }
        }
        #pragma unroll
        for (int i = 0; i < 16; ++i) {
            sNew[nl * 65 + h * 16 + i] = o[i];
            sKy [nl * 65 + h * 16 + i] = kv[i];
        }
    }
    __syncthreads();
    // phase 2: vp = sNew @ pV, 8 rows x 4 cols {cg,cg+16,cg+32,cg+48} per thread
    {
        int rg = tid >> 4, cg = tid & 15;
        float acc[8][4];
        #pragma unroll
        for (int a = 0; a < 8; ++a)
            #pragma unroll
            for (int b = 0; b < 4; ++b) acc[a][b] = 0.f;
        #pragma unroll 8
        for (int k = 0; k < 64; ++k) {
            float b0 = sPV[k * 64 + cg     ], b1 = sPV[k * 64 + cg + 16];
            float b2 = sPV[k * 64 + cg + 32], b3 = sPV[k * 64 + cg + 48];
            #pragma unroll
            for (int a = 0; a < 8; ++a) {
                float av = sNew[(rg * 8 + a) * 65 + k];
                acc[a][0] += av * b0; acc[a][1] += av * b1;
                acc[a][2] += av * b2; acc[a][3] += av * b3;
            }
        }
        #pragma unroll
        for (int a = 0; a < 8; ++a) {
            int rrow = rg * 8 + a;
            sVP[rrow * 65 + cg     ] = acc[a][0];
            sVP[rrow * 65 + cg + 16] = acc[a][1];
            sVP[rrow * 65 + cg + 32] = acc[a][2];
            sVP[rrow * 65 + cg + 48] = acc[a][3];
        }
    }
    __syncthreads();
    // phase 3: Gram
    {
        int hg = tid >> 6, pi = (tid >> 3) & 7, pj = tid & 7;
        int ca0 = hg * 16 + 2 * pi, cb0 = hg * 16 + 2 * pj;
        float g00 = 0.f, g01 = 0.f, g10 = 0.f, g11 = 0.f;
        #pragma unroll 8
        for (int r = 0; r < 128; ++r) {
            float va0 = sVP[r * 65 + ca0], va1 = sVP[r * 65 + ca0 + 1];
            float vb0 = sKy[r * 65 + cb0], vb1 = sKy[r * 65 + cb0 + 1];
            g00 += va0 * vb0; g01 += va0 * vb1;
            g10 += va1 * vb0; g11 += va1 * vb1;
        }
        atomicAdd(&VK[hg * 256 + (2 * pi    ) * 16 + 2 * pj    ], g00);
        atomicAdd(&VK[hg * 256 + (2 * pi    ) * 16 + 2 * pj + 1], g01);
        atomicAdd(&VK[hg * 256 + (2 * pi + 1) * 16 + 2 * pj    ], g10);
        atomicAdd(&VK[hg * 256 + (2 * pi + 1) * 16 + 2 * pj + 1], g11);
    }
}

// ---------------- batched final epilogue: lat += Key@pre1 ----------------
__global__ void newtotal_final_all_kernel(const float* K0, const float* K1, const float* K2,
                                          float* La, float* Lb, float* Lc)
{
    int t = blockIdx.y;
    int N = (t == 1) ? INUM : UN;
    if (blockIdx.x * 64 >= N) return;
    const float* Key = (t == 0) ? K0 : ((t == 1) ? K1 : K2);
    float* lat       = (t == 0) ? La : ((t == 1) ? Lb : Lc);
    const float* PRE = g_scr + t * 4096 + 3072;
    __shared__ float sPre[1024];
    int tid = threadIdx.x;
    for (int i = tid; i < 1024; i += 256) sPre[i] = PRE[i];
    __syncthreads();
    int n = blockIdx.x * 64 + (tid & 63);
    int h = tid >> 6;
    if (n >= N) return;
    const float4* kp = (const float4*)Key + ((size_t)h * N + n) * 4;
    float4 k0 = __ldg(kp), k1 = __ldg(kp + 1), k2 = __ldg(kp + 2), k3 = __ldg(kp + 3);
    float kv[16] = {k0.x,k0.y,k0.z,k0.w, k1.x,k1.y,k1.z,k1.w,
                    k2.x,k2.y,k2.z,k2.w, k3.x,k3.y,k3.z,k3.w};
    const float* pb = &sPre[h * 256];
    float o[16];
    #pragma unroll
    for (int j = 0; j < 16; ++j) {
        float s = 0.f;
        #pragma unroll
        for (int i = 0; i < 16; ++i) s += kv[i] * pb[i * 16 + j];
        o[j] = s;
    }
    size_t base = (size_t)n * 64 + h * 16;
    float4* lp = (float4*)(lat + base);
    #pragma unroll
    for (int q = 0; q < 4; ++q) {
        float4 e = lp[q];
        lp[q] = make_float4(e.x + o[q*4+0], e.y + o[q*4+1], e.z + o[q*4+2], e.w + o[q*4+3]);
    }
}

// ---------------- host launch ----------------
extern "C" void kernel_launch(void* const* d_in, const int* in_sizes, int n_in,
                              void* d_out, int out_size)
{
    (void)in_sizes; (void)n_in; (void)out_size;
    const float* uE  = (const float*)d_in[0];
    const float* iE  = (const float*)d_in[1];
    const float* Ks  = (const float*)d_in[2];
    const float* Hyp = (const float*)d_in[3];
    const float* Vm  = (const float*)d_in[4];
    const float* pVm = (const float*)d_in[5];
    const float* W1  = (const float*)d_in[6];
    const float* W2  = (const float*)d_in[7];
    float* out = (float*)d_out;

    float *sp, *scrp; unsigned* cntp;
    cudaGetSymbolAddress((void**)&sp,   g_spbuf);
    cudaGetSymbolAddress((void**)&scrp, g_scr);
    cudaGetSymbolAddress((void**)&cntp, g_cnt);

    static const int EMBED_SMEM = (4096 + 4096 + 3 * 64 * 65) * 4;    // 82688 B
    static const int NT_SMEM    = (1024 + 4096 + 3 * 128 * 65) * 4;   // 120320 B
    cudaFuncSetAttribute(embed_key_vk_kernel,    cudaFuncAttributeMaxDynamicSharedMemorySize, EMBED_SMEM);
    cudaFuncSetAttribute(newtotal_vk_all_kernel, cudaFuncAttributeMaxDynamicSharedMemorySize, NT_SMEM);

    // output offsets (floats)
    float* O_uE0   = out + 0;
    float* O_iE0   = out + 6400000;
    float* O_ulat  = out + 9600000;
    float* O_ilat  = out + 16000000;
    float* O_uKey  = out + 19200000;
    float* O_iKey  = out + 25600000;
    float* O_uHyp  = out + 28800000;
    float* O_iHyp  = out + 28808192;
    float* O_uuE0  = out + 28816384;
    float* O_uulat = out + 35216384;
    float* O_uuKey = out + 41616384;
    float* O_uuHyp = out + 48016384;

    // launch order chosen so ncu (-s 5 -c 1) captures gather hop-1 as launch #6
    route_kernel<<<49, 256>>>(d_in[8], d_in[9], d_in[10], d_in[11], d_in[12],
                              d_in[13], d_in[14], d_in[15], d_in[16]);          // 1
    cudaMemsetAsync(cntp, 0, (size_t)NROWS_TOT * sizeof(unsigned), 0);          // 2

    const int eGrid = (3 * NNZE + 255) / 256;
    hist3_kernel<<<eGrid, 256>>>();                                             // 3
    scan3_kernel<<<3, 1024>>>();                                                // 4
    scatter3_kernel<<<eGrid, 256>>>();                                          // 5

    const int gGrid = NROWS_TOT / 16;
    gather3_kernel<<<gGrid, 256>>>(iE, uE, uE, sp + Z_TU1, sp + Z_TI1, sp + Z_UU1);   // 6 (profiled)
    gather3_kernel<<<gGrid, 256>>>(sp + Z_TI1, sp + Z_TU1, sp + Z_UU1,
                                   sp + Z_TU2, sp + Z_TI2, sp + Z_UU2);

    copy_hyper_kernel<<<32, 256>>>(Hyp, O_uHyp, O_iHyp, O_uuHyp);

    embed_key_vk_kernel<<<1480, 256, EMBED_SMEM>>>(uE, sp + Z_TU1, sp + Z_TU2, Ks + 0,
                                                   pVm + 0,    O_uE0,  O_uKey,  scrp + 0 * 4096, UN);
    embed_key_vk_kernel<<<1480, 256, EMBED_SMEM>>>(iE, sp + Z_TI1, sp + Z_TI2, Ks + 4096,
                                                   pVm + 4096, O_iE0,  O_iKey,  scrp + 1 * 4096, INUM);
    embed_key_vk_kernel<<<1480, 256, EMBED_SMEM>>>(uE, sp + Z_UU1, sp + Z_UU2, Ks + 8192,
                                                   pVm + 8192, O_uuE0, O_uuKey, scrp + 2 * 4096, UN);

    dim3 smallGrid(16, 3);
    dim3 rowGrid128((UN + 127) / 128, 3);
    dim3 rowGrid64((UN + 63) / 64, 3);

    // layer 0
    t1t2_all_kernel<<<smallGrid, 256>>>(Hyp, W1, 0);
    t3pre_all_kernel<<<smallGrid, 256>>>(W2, Vm, Hyp, 0);
    newtotal_vk_all_kernel<<<rowGrid128, 256, NT_SMEM>>>(O_uKey, O_iKey, O_uuKey,
                                                         O_uE0, O_iE0, O_uuE0,
                                                         O_ulat, O_ilat, O_uulat, pVm);
    // layer 1
    t1t2_all_kernel<<<smallGrid, 256>>>(Hyp, W1, 1);
    t3pre_all_kernel<<<smallGrid, 256>>>(W2, Vm, Hyp, 1);
    newtotal_final_all_kernel<<<rowGrid64, 256>>>(O_uKey, O_iKey, O_uuKey,
                                                  O_ulat, O_ilat, O_uulat);
}

// round 8
// speedup vs baseline: 1.1292x; 1.1292x over previous
#include <cuda_runtime.h>

// ---------------- problem constants ----------------
#define UN   100000
#define INUM 50000
#define NNZE 1000000
#define NROWS_TOT (UN + INUM + UN)     // 250000

// ---------------- routed sparse pointers ----------------
__device__ const int*   g_rows[3];
__device__ const int*   g_cols[3];
__device__ const float* g_vals[3];

// ---------------- scratch ----------------
__device__ unsigned g_cnt[NROWS_TOT];          // zeroed in route kernel
__device__ float    g_scr[3 * 4096];           // zeroed in route kernel
__device__ unsigned g_slot[3 * NNZE];
__device__ unsigned g_rowstart[NROWS_TOT + 3];
__device__ unsigned long long g_csr[3 * NNZE]; // packed (val<<32 | col)
__device__ float    g_spbuf[32000000];
__device__ float    g_t2[3 * 8192];

#define Z_TU1 0
#define Z_TU2 6400000
#define Z_UU1 12800000
#define Z_UU2 19200000
#define Z_TI1 25600000
#define Z_TI2 28800000

// ---------------- router + zero g_cnt + zero g_scr (one launch) ----------------
// blocks 0..1024 zero (g_cnt | g_scr); last block routes pointers.
__global__ void route_kernel(const void* a8, const void* a9, const void* a10,
                             const void* a11, const void* a12, const void* a13,
                             const void* a14, const void* a15, const void* a16)
{
    int b = blockIdx.x;
    if (b < 977) {                       // 977*256 = 250112 >= 250000
        int i = b * 256 + threadIdx.x;
        if (i < NROWS_TOT) g_cnt[i] = 0u;
        return;
    }
    if (b < 1025) {                      // 48 blocks for g_scr (12288 floats)
        int i = (b - 977) * 256 + threadIdx.x;
        if (i < 3 * 4096) g_scr[i] = 0.f;
        return;
    }
    if (threadIdx.x != 0) return;
    const unsigned* p = (const unsigned*)a8;
    unsigned m = 0;
    for (int i = 0; i < 32; ++i) { unsigned v = p[i]; m = (v > m) ? v : m; }
    if (m > 0x01000000u) {
        g_vals[0] = (const float*)a8;  g_vals[1] = (const float*)a9;  g_vals[2] = (const float*)a10;
        g_rows[0] = (const int*)a11;   g_cols[0] = (const int*)a12;
        g_rows[1] = (const int*)a13;   g_cols[1] = (const int*)a14;
        g_rows[2] = (const int*)a15;   g_cols[2] = (const int*)a16;
    } else {
        g_rows[0] = (const int*)a8;   g_cols[0] = (const int*)a9;   g_vals[0] = (const float*)a10;
        g_rows[1] = (const int*)a11;  g_cols[1] = (const int*)a12;  g_vals[1] = (const float*)a13;
        g_rows[2] = (const int*)a14;  g_cols[2] = (const int*)a15;  g_vals[2] = (const float*)a16;
    }
}

// ---------------- CSR build: histogram + record slot ----------------
__global__ void hist3_kernel()
{
    int e = blockIdx.x * 256 + threadIdx.x;
    if (e >= 3 * NNZE) return;
    int m = (e >= 2 * NNZE) ? 2 : ((e >= NNZE) ? 1 : 0);
    int i = e - m * NNZE;
    int cb = (m == 0) ? 0 : ((m == 1) ? UN : UN + INUM);
    int r = __ldg(&g_rows[m][i]);
    g_slot[e] = atomicAdd(&g_cnt[cb + r], 1u);
}

// ---------------- CSR build: 3 exclusive scans (one block each) ----------------
__global__ void scan3_kernel()
{
    __shared__ unsigned sPart[1024];
    int m = blockIdx.x;
    int Nm  = (m == 1) ? INUM : UN;
    int cb  = (m == 0) ? 0 : ((m == 1) ? UN : UN + INUM);
    int rb  = (m == 0) ? 0 : ((m == 1) ? UN + 1 : UN + INUM + 2);
    int t = threadIdx.x;
    int chunk = (Nm + 1023) >> 10;
    int lo = t * chunk; if (lo > Nm) lo = Nm;
    int hi = lo + chunk; if (hi > Nm) hi = Nm;
    unsigned s = 0;
    for (int i = lo; i < hi; ++i) s += g_cnt[cb + i];
    sPart[t] = s;
    __syncthreads();
    for (int d = 1; d < 1024; d <<= 1) {
        unsigned v = (t >= d) ? sPart[t - d] : 0u;
        __syncthreads();
        sPart[t] += v;
        __syncthreads();
    }
    unsigned run = (t == 0) ? 0u : sPart[t - 1];
    for (int i = lo; i < hi; ++i) {
        unsigned c = g_cnt[cb + i];
        g_rowstart[rb + i] = run;
        run += c;
    }
    if (t == 1023) g_rowstart[rb + Nm] = run;
}

// ---------------- CSR build: scatter (no atomics) ----------------
__global__ void scatter3_kernel()
{
    int e = blockIdx.x * 256 + threadIdx.x;
    if (e >= 3 * NNZE) return;
    int m = (e >= 2 * NNZE) ? 2 : ((e >= NNZE) ? 1 : 0);
    int i = e - m * NNZE;
    int rb = (m == 0) ? 0 : ((m == 1) ? UN + 1 : UN + INUM + 2);
    int   r = __ldg(&g_rows[m][i]);
    int   c = __ldg(&g_cols[m][i]);
    float v = __ldg(&g_vals[m][i]);
    unsigned idx = __ldg(&g_rowstart[rb + r]) + g_slot[e];
    g_csr[(size_t)m * NNZE + idx] =
        ((unsigned long long)__float_as_uint(v) << 32) | (unsigned)c;
}

// ---------------- gather SpMM: 3 matrices, 16 lanes per row, no atomics, 4-wide ILP ----------------
__global__ void __launch_bounds__(256) gather3_kernel(
    const float* __restrict__ X0, const float* __restrict__ X1, const float* __restrict__ X2,
    float* __restrict__ O0, float* __restrict__ O1, float* __restrict__ O2)
{
    int gr = blockIdx.x * 16 + (threadIdx.x >> 4);
    int lane = threadIdx.x & 15;
    int m, r, rb;
    const float* X; float* O;
    if (gr < UN)              { m = 0; r = gr;             rb = 0;              X = X0; O = O0; }
    else if (gr < UN + INUM)  { m = 1; r = gr - UN;        rb = UN + 1;         X = X1; O = O1; }
    else                      { m = 2; r = gr - UN - INUM; rb = UN + INUM + 2;  X = X2; O = O2; }
    unsigned s = __ldg(&g_rowstart[rb + r]);
    unsigned e = __ldg(&g_rowstart[rb + r + 1]);
    const unsigned long long* csr = g_csr + (size_t)m * NNZE;
    float4 accA = make_float4(0.f, 0.f, 0.f, 0.f);
    float4 accB = make_float4(0.f, 0.f, 0.f, 0.f);
    unsigned i = s;
    for (; i + 4 <= e; i += 4) {
        unsigned long long u0 = __ldg(&csr[i]);
        unsigned long long u1 = __ldg(&csr[i + 1]);
        unsigned long long u2 = __ldg(&csr[i + 2]);
        unsigned long long u3 = __ldg(&csr[i + 3]);
        float4 x0 = __ldg((const float4*)X + (size_t)(unsigned)(u0 & 0xffffffffu) * 16 + lane);
        float4 x1 = __ldg((const float4*)X + (size_t)(unsigned)(u1 & 0xffffffffu) * 16 + lane);
        float4 x2 = __ldg((const float4*)X + (size_t)(unsigned)(u2 & 0xffffffffu) * 16 + lane);
        float4 x3 = __ldg((const float4*)X + (size_t)(unsigned)(u3 & 0xffffffffu) * 16 + lane);
        float v0 = __uint_as_float((unsigned)(u0 >> 32));
        float v1 = __uint_as_float((unsigned)(u1 >> 32));
        float v2 = __uint_as_float((unsigned)(u2 >> 32));
        float v3 = __uint_as_float((unsigned)(u3 >> 32));
        accA.x += v0 * x0.x; accA.y += v0 * x0.y; accA.z += v0 * x0.z; accA.w += v0 * x0.w;
        accB.x += v1 * x1.x; accB.y += v1 * x1.y; accB.z += v1 * x1.z; accB.w += v1 * x1.w;
        accA.x += v2 * x2.x; accA.y += v2 * x2.y; accA.z += v2 * x2.z; accA.w += v2 * x2.w;
        accB.x += v3 * x3.x; accB.y += v3 * x3.y; accB.z += v3 * x3.z; accB.w += v3 * x3.w;
    }
    for (; i < e; ++i) {
        unsigned long long u0 = __ldg(&csr[i]);
        float v0 = __uint_as_float((unsigned)(u0 >> 32));
        float4 x0 = __ldg((const float4*)X + (size_t)(unsigned)(u0 & 0xffffffffu) * 16 + lane);
        accA.x += v0 * x0.x; accA.y += v0 * x0.y; accA.z += v0 * x0.z; accA.w += v0 * x0.w;
    }
    ((float4*)O)[(size_t)r * 16 + lane] =
        make_float4(accA.x + accB.x, accA.y + accB.y, accA.z + accB.z, accA.w + accB.w);
}

// ---------------- copy the 3 Hyper outputs ----------------
__global__ void copy_hyper_kernel(const float* __restrict__ Hyp,
                                  float* o0, float* o1, float* o2)
{
    int i = blockIdx.x * 256 + threadIdx.x;
    if (i < 8192) { o0[i] = Hyp[i]; o1[i] = Hyp[8192 + i]; o2[i] = Hyp[16384 + i]; }
}

// ---------------- fused embed+key+vp+Gram, BATCHED over 3 transformers (R6 tiles: 32-row) ----------------
// smem floats: sK[4096] | sPV[4096] | sE[32*65] | sKy[32*65] | sVP[32*65]  = 57728 B (3 blocks/SM)
__global__ void __launch_bounds__(256) embed_key_vk_all_kernel(
    const float* __restrict__ uE, const float* __restrict__ iE,
    const float* __restrict__ Ks, const float* __restrict__ pVm,
    float* __restrict__ spb,
    float* E0a, float* E0b, float* E0c,
    float* Ka,  float* Kb,  float* Kc)
{
    int t = blockIdx.y;
    int N = (t == 1) ? INUM : UN;
    const float* A  = (t == 1) ? iE : uE;
    const float* B1 = (t == 0) ? (spb + Z_TU1) : ((t == 1) ? (spb + Z_TI1) : (spb + Z_UU1));
    const float* B2 = (t == 0) ? (spb + Z_TU2) : ((t == 1) ? (spb + Z_TI2) : (spb + Z_UU2));
    const float* Kmat = Ks + t * 4096;
    const float* pV   = pVm + t * 4096;
    float* E0  = (t == 0) ? E0a : ((t == 1) ? E0b : E0c);
    float* Key = (t == 0) ? Ka  : ((t == 1) ? Kb  : Kc);
    float* VK  = g_scr + t * 4096;

    extern __shared__ float sm[];
    float* sK  = sm;
    float* sPV = sm + 4096;
    float* sE  = sm + 8192;          // [32][65]
    float* sKy = sE + 32 * 65;
    float* sVP = sKy + 32 * 65;
    int tid = threadIdx.x;
    for (int i = tid; i < 4096; i += 256) { sK[i] = Kmat[i]; sPV[i] = pV[i]; }
    int rq = tid >> 5;
    int tx = tid & 31;
    int c0 = tx, c1 = tx + 32;
    int hg = tid >> 6, pi = (tid >> 3) & 7, pj = tid & 7;
    float g00 = 0.f, g01 = 0.f, g10 = 0.f, g11 = 0.f;
    __syncthreads();
    int nChunks = (N + 31) >> 5;
    for (int chunk = blockIdx.x; chunk < nChunks; chunk += gridDim.x) {
        int n0 = chunk << 5;
        #pragma unroll
        for (int q = 0; q < 2; ++q) {
            int idx = tid + q * 256;
            int r = idx >> 4, cc = idx & 15;
            int n = n0 + r;
            float4 v = make_float4(0.f, 0.f, 0.f, 0.f);
            if (n < N) {
                float4 a = __ldg((const float4*)A  + (size_t)n * 16 + cc);
                float4 b = __ldg((const float4*)B1 + (size_t)n * 16 + cc);
                float4 d = __ldg((const float4*)B2 + (size_t)n * 16 + cc);
                v = make_float4(a.x + b.x + d.x, a.y + b.y + d.y,
                                a.z + b.z + d.z, a.w + b.w + d.w);
                ((float4*)E0)[(size_t)n * 16 + cc] = v;
            }
            sE[r * 65 + cc * 4 + 0] = v.x; sE[r * 65 + cc * 4 + 1] = v.y;
            sE[r * 65 + cc * 4 + 2] = v.z; sE[r * 65 + cc * 4 + 3] = v.w;
        }
        __syncthreads();
        float ka[4][2] = {{0.f,0.f},{0.f,0.f},{0.f,0.f},{0.f,0.f}};
        float pa[4][2] = {{0.f,0.f},{0.f,0.f},{0.f,0.f},{0.f,0.f}};
        #pragma unroll 16
        for (int k = 0; k < 64; ++k) {
            float w0 = sK[k * 64 + c0],  w1 = sK[k * 64 + c1];
            float p0 = sPV[k * 64 + c0], p1 = sPV[k * 64 + c1];
            #pragma unroll
            for (int rr = 0; rr < 4; ++rr) {
                float ev = sE[(rq * 4 + rr) * 65 + k];
                ka[rr][0] += ev * w0; ka[rr][1] += ev * w1;
                pa[rr][0] += ev * p0; pa[rr][1] += ev * p1;
            }
        }
        int h0 = c0 >> 4, j0 = c0 & 15, h1 = c1 >> 4, j1 = c1 & 15;
        size_t kb0 = (size_t)h0 * N * 16, kb1 = (size_t)h1 * N * 16;
        #pragma unroll
        for (int rr = 0; rr < 4; ++rr) {
            int rrow = rq * 4 + rr;
            sKy[rrow * 65 + c0] = ka[rr][0]; sKy[rrow * 65 + c1] = ka[rr][1];
            sVP[rrow * 65 + c0] = pa[rr][0]; sVP[rrow * 65 + c1] = pa[rr][1];
            int n = n0 + rrow;
            if (n < N) {
                Key[kb0 + (size_t)n * 16 + j0] = ka[rr][0];
                Key[kb1 + (size_t)n * 16 + j1] = ka[rr][1];
            }
        }
        __syncthreads();
        int ca0 = hg * 16 + 2 * pi, cb0 = hg * 16 + 2 * pj;
        #pragma unroll
        for (int r = 0; r < 32; ++r) {
            float va0 = sVP[r * 65 + ca0], va1 = sVP[r * 65 + ca0 + 1];
            float vb0 = sKy[r * 65 + cb0], vb1 = sKy[r * 65 + cb0 + 1];
            g00 += va0 * vb0; g01 += va0 * vb1;
            g10 += va1 * vb0; g11 += va1 * vb1;
        }
        __syncthreads();
    }
    atomicAdd(&VK[hg * 256 + (2 * pi    ) * 16 + 2 * pj    ], g00);
    atomicAdd(&VK[hg * 256 + (2 * pi    ) * 16 + 2 * pj + 1], g01);
    atomicAdd(&VK[hg * 256 + (2 * pi + 1) * 16 + 2 * pj    ], g10);
    atomicAdd(&VK[hg * 256 + (2 * pi + 1) * 16 + 2 * pj + 1], g11);
}

__device__ __forceinline__ float leaky_f(float x) { return (x >= 0.f) ? x : 0.5f * x; }

// ---------------- batched t1t2 ----------------
__global__ void t1t2_all_kernel(const float* __restrict__ Hyp, const float* __restrict__ W1base,
                                int layer)
{
    __shared__ float sVK[1024];
    __shared__ float sT1[8192];
    int t = blockIdx.y;
    const float* VK    = g_scr + t * 4096 + layer * 1024;
    const float* Hyper = Hyp + t * 8192;
    const float* W1    = W1base + (size_t)(t * 2 + layer) * 16384;
    float* T2out       = g_t2 + t * 8192;
    int tid = threadIdx.x;
    for (int i = tid; i < 1024; i += 256) sVK[i] = VK[i];
    __syncthreads();
    for (int o = tid; o < 8192; o += 256) {
        int d = o >> 7, k = o & 127;
        int h = d >> 4, i = d & 15;
        float s = 0.f;
        #pragma unroll
        for (int j = 0; j < 16; ++j)
            s += sVK[h * 256 + i * 16 + j] * __ldg(&Hyper[k * 64 + h * 16 + j]);
        sT1[d * 128 + k] = s;
    }
    __syncthreads();
    int kb = blockIdx.x * 8;
    for (int o = tid; o < 512; o += 256) {
        int d = o >> 3, k = kb + (o & 7);
        float s = 0.f;
        #pragma unroll 8
        for (int m = 0; m < 128; ++m) s += sT1[d * 128 + m] * __ldg(&W1[k * 128 + m]);
        T2out[d * 128 + k] = leaky_f(s) + sT1[d * 128 + k];
    }
}

// ---------------- batched t3+pre ----------------
__global__ void t3pre_all_kernel(const float* __restrict__ W2base, const float* __restrict__ Vbase,
                                 const float* __restrict__ Hyp, int layer)
{
    __shared__ float sT2[8192];
    __shared__ float sT3[8][64];
    __shared__ float sP0[8][64];
    int t = blockIdx.y;
    const float* T2    = g_t2 + t * 8192;
    const float* W2    = W2base + (size_t)(t * 2 + layer) * 16384;
    const float* V     = Vbase + t * 4096;
    const float* Hyper = Hyp + t * 8192;
    float* PRE         = g_scr + t * 4096 + 2048 + layer * 1024;
    int tid = threadIdx.x;
    for (int i = tid; i < 8192; i += 256) sT2[i] = T2[i];
    __syncthreads();
    int kb = blockIdx.x * 8;
    for (int o = tid; o < 512; o += 256) {
        int d = o >> 3, kk = o & 7, k = kb + kk;
        float s = 0.f;
        #pragma unroll 8
        for (int m = 0; m < 128; ++m) s += sT2[d * 128 + m] * __ldg(&W2[k * 128 + m]);
        sT3[kk][d] = leaky_f(s) + sT2[d * 128 + k];
    }
    __syncthreads();
    for (int o = tid; o < 512; o += 256) {
        int kk = o >> 6, d2 = o & 63;
        float s = 0.f;
        #pragma unroll 8
        for (int d = 0; d < 64; ++d) s += sT3[kk][d] * __ldg(&V[d * 64 + d2]);
        sP0[kk][d2] = s;
    }
    __syncthreads();
    for (int o = tid; o < 1024; o += 256) {
        int h = o >> 8, i = (o >> 4) & 15, j = o & 15;
        float s = 0.f;
        #pragma unroll
        for (int kk = 0; kk < 8; ++kk)
            s += __ldg(&Hyper[(size_t)(kb + kk) * 64 + h * 16 + i]) * sP0[kk][h * 16 + j];
        atomicAdd(&PRE[o], s);
    }
}

// ---------------- batched layer-0 epilogue + layer-1 prologue (R6 tiles: 64 rows/block) ----------------
// smem floats: sPre[1024] | sPV[4096] | sNew[64*65] | sKy[64*65] | sVP[64*65] = 70400 B (3 blocks/SM)
__global__ void __launch_bounds__(256) newtotal_vk_all_kernel(
    const float* K0, const float* K1, const float* K2,
    const float* E0a, const float* E0b, const float* E0c,
    float* La, float* Lb, float* Lc,
    const float* __restrict__ pVbase)
{
    int t = blockIdx.y;
    int N = (t == 1) ? INUM : UN;
    if (blockIdx.x * 64 >= N) return;
    const float* Key = (t == 0) ? K0 : ((t == 1) ? K1 : K2);
    const float* E0  = (t == 0) ? E0a : ((t == 1) ? E0b : E0c);
    float* lat       = (t == 0) ? La : ((t == 1) ? Lb : Lc);
    const float* PRE = g_scr + t * 4096 + 2048;
    const float* pV  = pVbase + t * 4096;
    float* VK        = g_scr + t * 4096 + 1024;

    extern __shared__ float sm[];
    float* sPre = sm;
    float* sPV  = sm + 1024;
    float* sNew = sm + 5120;             // [64][65]
    float* sKy  = sNew + 64 * 65;
    float* sVP  = sKy + 64 * 65;
    int tid = threadIdx.x;
    for (int i = tid; i < 1024; i += 256) sPre[i] = PRE[i];
    for (int i = tid; i < 4096; i += 256) sPV[i] = pV[i];
    __syncthreads();
    int nl = tid & 63, h = tid >> 6;
    int n = blockIdx.x * 64 + nl;
    bool valid = (n < N);
    float kv[16];
    #pragma unroll
    for (int i = 0; i < 16; ++i) kv[i] = 0.f;
    if (valid) {
        const float4* kp = (const float4*)Key + ((size_t)h * N + n) * 4;
        float4 k0 = __ldg(kp), k1 = __ldg(kp + 1), k2 = __ldg(kp + 2), k3 = __ldg(kp + 3);
        kv[0]=k0.x; kv[1]=k0.y; kv[2]=k0.z; kv[3]=k0.w;
        kv[4]=k1.x; kv[5]=k1.y; kv[6]=k1.z; kv[7]=k1.w;
        kv[8]=k2.x; kv[9]=k2.y; kv[10]=k2.z; kv[11]=k2.w;
        kv[12]=k3.x; kv[13]=k3.y; kv[14]=k3.z; kv[15]=k3.w;
    }
    const float* pb = &sPre[h * 256];
    float o[16];
    #pragma unroll
    for (int j = 0; j < 16; ++j) {
        float s = 0.f;
        #pragma unroll
        for (int i = 0; i < 16; ++i) s += kv[i] * pb[i * 16 + j];
        o[j] = s;
    }
    if (valid) {
        size_t base = (size_t)n * 64 + h * 16;
        const float4* ep = (const float4*)(E0 + base);
        float4* lp = (float4*)(lat + base);
        #pragma unroll
        for (int q = 0; q < 4; ++q) {
            float4 e = __ldg(ep + q);
            lp[q] = make_float4(e.x + o[q*4+0], e.y + o[q*4+1], e.z + o[q*4+2], e.w + o[q*4+3]);
        }
    }
    #pragma unroll
    for (int i = 0; i < 16; ++i) {
        sNew[nl * 65 + h * 16 + i] = o[i];
        sKy [nl * 65 + h * 16 + i] = kv[i];
    }
    __syncthreads();
    {
        int ty = tid >> 4, tx = tid & 15, cb = tx * 4;
        float acc[4][4];
        #pragma unroll
        for (int a = 0; a < 4; ++a)
            #pragma unroll
            for (int b = 0; b < 4; ++b) acc[a][b] = 0.f;
        #pragma unroll 16
        for (int k = 0; k < 64; ++k) {
            float b0 = sPV[k * 64 + cb + 0], b1 = sPV[k * 64 + cb + 1];
            float b2 = sPV[k * 64 + cb + 2], b3 = sPV[k * 64 + cb + 3];
            #pragma unroll
            for (int a = 0; a < 4; ++a) {
                float av = sNew[(ty * 4 + a) * 65 + k];
                acc[a][0] += av * b0; acc[a][1] += av * b1;
                acc[a][2] += av * b2; acc[a][3] += av * b3;
            }
        }
        #pragma unroll
        for (int a = 0; a < 4; ++a)
            #pragma unroll
            for (int b = 0; b < 4; ++b)
                sVP[(ty * 4 + a) * 65 + cb + b] = acc[a][b];
    }
    __syncthreads();
    {
        int hg = tid >> 6, pi = (tid >> 3) & 7, pj = tid & 7;
        int ca0 = hg * 16 + 2 * pi, cb0 = hg * 16 + 2 * pj;
        float g00 = 0.f, g01 = 0.f, g10 = 0.f, g11 = 0.f;
        #pragma unroll 16
        for (int r = 0; r < 64; ++r) {
            float va0 = sVP[r * 65 + ca0], va1 = sVP[r * 65 + ca0 + 1];
            float vb0 = sKy[r * 65 + cb0], vb1 = sKy[r * 65 + cb0 + 1];
            g00 += va0 * vb0; g01 += va0 * vb1;
            g10 += va1 * vb0; g11 += va1 * vb1;
        }
        atomicAdd(&VK[hg * 256 + (2 * pi    ) * 16 + 2 * pj    ], g00);
        atomicAdd(&VK[hg * 256 + (2 * pi    ) * 16 + 2 * pj + 1], g01);
        atomicAdd(&VK[hg * 256 + (2 * pi + 1) * 16 + 2 * pj    ], g10);
        atomicAdd(&VK[hg * 256 + (2 * pi + 1) * 16 + 2 * pj + 1], g11);
    }
}

// ---------------- batched final epilogue: lat += Key@pre1 ----------------
__global__ void newtotal_final_all_kernel(const float* K0, const float* K1, const float* K2,
                                          float* La, float* Lb, float* Lc)
{
    int t = blockIdx.y;
    int N = (t == 1) ? INUM : UN;
    if (blockIdx.x * 64 >= N) return;
    const float* Key = (t == 0) ? K0 : ((t == 1) ? K1 : K2);
    float* lat       = (t == 0) ? La : ((t == 1) ? Lb : Lc);
    const float* PRE = g_scr + t * 4096 + 3072;
    __shared__ float sPre[1024];
    int tid = threadIdx.x;
    for (int i = tid; i < 1024; i += 256) sPre[i] = PRE[i];
    __syncthreads();
    int n = blockIdx.x * 64 + (tid & 63);
    int h = tid >> 6;
    if (n >= N) return;
    const float4* kp = (const float4*)Key + ((size_t)h * N + n) * 4;
    float4 k0 = __ldg(kp), k1 = __ldg(kp + 1), k2 = __ldg(kp + 2), k3 = __ldg(kp + 3);
    float kv[16] = {k0.x,k0.y,k0.z,k0.w, k1.x,k1.y,k1.z,k1.w,
                    k2.x,k2.y,k2.z,k2.w, k3.x,k3.y,k3.z,k3.w};
    const float* pb = &sPre[h * 256];
    float o[16];
    #pragma unroll
    for (int j = 0; j < 16; ++j) {
        float s = 0.f;
        #pragma unroll
        for (int i = 0; i < 16; ++i) s += kv[i] * pb[i * 16 + j];
        o[j] = s;
    }
    size_t base = (size_t)n * 64 + h * 16;
    float4* lp = (float4*)(lat + base);
    #pragma unroll
    for (int q = 0; q < 4; ++q) {
        float4 e = lp[q];
        lp[q] = make_float4(e.x + o[q*4+0], e.y + o[q*4+1], e.z + o[q*4+2], e.w + o[q*4+3]);
    }
}

// ---------------- host launch ----------------
extern "C" void kernel_launch(void* const* d_in, const int* in_sizes, int n_in,
                              void* d_out, int out_size)
{
    (void)in_sizes; (void)n_in; (void)out_size;
    const float* uE  = (const float*)d_in[0];
    const float* iE  = (const float*)d_in[1];
    const float* Ks  = (const float*)d_in[2];
    const float* Hyp = (const float*)d_in[3];
    const float* Vm  = (const float*)d_in[4];
    const float* pVm = (const float*)d_in[5];
    const float* W1  = (const float*)d_in[6];
    const float* W2  = (const float*)d_in[7];
    float* out = (float*)d_out;

    float* sp;
    cudaGetSymbolAddress((void**)&sp, g_spbuf);

    static const int EMBED_SMEM = (4096 + 4096 + 3 * 32 * 65) * 4;   // 57728 B
    static const int NT_SMEM    = (1024 + 4096 + 3 * 64 * 65) * 4;   // 70400 B
    cudaFuncSetAttribute(embed_key_vk_all_kernel, cudaFuncAttributeMaxDynamicSharedMemorySize, EMBED_SMEM);
    cudaFuncSetAttribute(newtotal_vk_all_kernel,  cudaFuncAttributeMaxDynamicSharedMemorySize, NT_SMEM);

    // output offsets (floats)
    float* O_uE0   = out + 0;
    float* O_iE0   = out + 6400000;
    float* O_ulat  = out + 9600000;
    float* O_ilat  = out + 16000000;
    float* O_uKey  = out + 19200000;
    float* O_iKey  = out + 25600000;
    float* O_uHyp  = out + 28800000;
    float* O_iHyp  = out + 28808192;
    float* O_uuE0  = out + 28816384;
    float* O_uulat = out + 35216384;
    float* O_uuKey = out + 41616384;
    float* O_uuHyp = out + 48016384;

    // launches: 1 route(+zero), 2 hist, 3 scan, 4 scatter, 5 gather (profiled), ...
    route_kernel<<<1026, 256>>>(d_in[8], d_in[9], d_in[10], d_in[11], d_in[12],
                                d_in[13], d_in[14], d_in[15], d_in[16]);

    const int eGrid = (3 * NNZE + 255) / 256;
    hist3_kernel<<<eGrid, 256>>>();
    scan3_kernel<<<3, 1024>>>();
    scatter3_kernel<<<eGrid, 256>>>();

    const int gGrid = NROWS_TOT / 16;
    gather3_kernel<<<gGrid, 256>>>(iE, uE, uE, sp + Z_TU1, sp + Z_TI1, sp + Z_UU1);
    gather3_kernel<<<gGrid, 256>>>(sp + Z_TI1, sp + Z_TU1, sp + Z_UU1,
                                   sp + Z_TU2, sp + Z_TI2, sp + Z_UU2);

    copy_hyper_kernel<<<32, 256>>>(Hyp, O_uHyp, O_iHyp, O_uuHyp);

    dim3 embedGrid(1480, 3);
    embed_key_vk_all_kernel<<<embedGrid, 256, EMBED_SMEM>>>(uE, iE, Ks, pVm, sp,
                                                            O_uE0, O_iE0, O_uuE0,
                                                            O_uKey, O_iKey, O_uuKey);

    dim3 smallGrid(16, 3);
    dim3 rowGrid64((UN + 63) / 64, 3);

    // layer 0
    t1t2_all_kernel<<<smallGrid, 256>>>(Hyp, W1, 0);
    t3pre_all_kernel<<<smallGrid, 256>>>(W2, Vm, Hyp, 0);
    newtotal_vk_all_kernel<<<rowGrid64, 256, NT_SMEM>>>(O_uKey, O_iKey, O_uuKey,
                                                        O_uE0, O_iE0, O_uuE0,
                                                        O_ulat, O_ilat, O_uulat, pVm);
    // layer 1
    t1t2_all_kernel<<<smallGrid, 256>>>(Hyp, W1, 1);
    t3pre_all_kernel<<<smallGrid, 256>>>(W2, Vm, Hyp, 1);
    newtotal_final_all_kernel<<<rowGrid64, 256>>>(O_uKey, O_iKey, O_uuKey,
                                                  O_ulat, O_ilat, O_uulat);
}